// round 10
// baseline (speedup 1.0000x reference)
#include <cuda_runtime.h>
#include <cuda_bf16.h>
#include <math.h>
#include <stdint.h>

// Problem constants
#define T_TOKENS 16384
#define DDIM     1024
#define NEXP     8

// GEMM tiling
#define BM 128
#define BN 64
#define BK 32
#define LDR 40                     // bf16 elems per smem row (32 data + 8 pad = 80B)
#define NSTAGE 3
#define NITER (DDIM / BK)          // 32

// stage layout (bytes): Ah | Al | Bh | Bl
#define A_BYTES (BM * LDR * 2)     // 10240
#define B_BYTES (BN * LDR * 2)     // 5120
#define OFF_AH 0
#define OFF_AL A_BYTES
#define OFF_BH (2 * A_BYTES)
#define OFF_BL (2 * A_BYTES + B_BYTES)
#define STAGE_BYTES (2 * A_BYTES + 2 * B_BYTES)    // 30720
#define SMEM_DYN (NSTAGE * STAGE_BYTES)            // 92160

// ---------------- scratch (static device globals; no allocation) ------------
__device__ int    g_count[NEXP];
__device__ int    g_base[NEXP];
__device__ int    g_tok[NEXP][T_TOKENS];
__device__ int4   g_assign[T_TOKENS];
__device__ float2 g_tw[T_TOKENS];

__device__ __nv_bfloat16 g_xh[T_TOKENS * DDIM];
__device__ __nv_bfloat16 g_xl[T_TOKENS * DDIM];
__device__ __nv_bfloat16 g_w1h[NEXP * DDIM * DDIM];
__device__ __nv_bfloat16 g_w1l[NEXP * DDIM * DDIM];
__device__ __nv_bfloat16 g_w2h[NEXP * DDIM * DDIM];
__device__ __nv_bfloat16 g_w2l[NEXP * DDIM * DDIM];
__device__ __nv_bfloat16 g_Hh[2 * T_TOKENS * DDIM];
__device__ __nv_bfloat16 g_Hl[2 * T_TOKENS * DDIM];
__device__ float         g_Y[2 * T_TOKENS * DDIM];

// ---------------- helpers ----------------------------------------------------
static __device__ __forceinline__ uint32_t smem_u32(const void* p) {
    uint32_t a;
    asm("{ .reg .u64 t; cvta.to.shared.u64 t, %1; cvt.u32.u64 %0, t; }"
        : "=r"(a) : "l"(p));
    return a;
}
static __device__ __forceinline__ void cp16(uint32_t dst, const void* src) {
    asm volatile("cp.async.cg.shared.global [%0], [%1], 16;" :: "r"(dst), "l"(src));
}
static __device__ __forceinline__ void cp_commit() {
    asm volatile("cp.async.commit_group;" ::: "memory");
}
static __device__ __forceinline__ void cp_wait1() {
    asm volatile("cp.async.wait_group 1;" ::: "memory");
}

static __device__ __forceinline__ void ldsm4(uint32_t* r, const __nv_bfloat16* p) {
    uint32_t a = (uint32_t)__cvta_generic_to_shared(p);
    asm volatile("ldmatrix.sync.aligned.m8n8.x4.shared.b16 {%0,%1,%2,%3}, [%4];"
                 : "=r"(r[0]), "=r"(r[1]), "=r"(r[2]), "=r"(r[3])
                 : "r"(a));
}
static __device__ __forceinline__ void mma16816(float* c, const uint32_t* a, const uint32_t* b) {
    asm volatile("mma.sync.aligned.m16n8k16.row.col.f32.bf16.bf16.f32 "
                 "{%0,%1,%2,%3},{%4,%5,%6,%7},{%8,%9},{%0,%1,%2,%3};"
                 : "+f"(c[0]), "+f"(c[1]), "+f"(c[2]), "+f"(c[3])
                 : "r"(a[0]), "r"(a[1]), "r"(a[2]), "r"(a[3]),
                   "r"(b[0]), "r"(b[1]));
}

// ---------------- init ------------------------------------------------------
__global__ void init_counts_kernel() {
    if (threadIdx.x < NEXP) {
        g_count[threadIdx.x] = 0;
    }
}

// ---------------- fp32 -> bf16 hi/lo split conversion ------------------------
__global__ void conv_split_kernel(const float* __restrict__ src, int which, int n4) {
    __nv_bfloat16* hi;
    __nv_bfloat16* lo;
    if (which == 0)      { hi = g_xh;  lo = g_xl;  }
    else if (which == 1) { hi = g_w1h; lo = g_w1l; }
    else                 { hi = g_w2h; lo = g_w2l; }

    int idx = blockIdx.x * blockDim.x + threadIdx.x;
    const int stride = gridDim.x * blockDim.x;
    for (; idx < n4; idx += stride) {
        float4 v = ((const float4*)src)[idx];
        __nv_bfloat16 h0 = __float2bfloat16_rn(v.x);
        __nv_bfloat16 h1 = __float2bfloat16_rn(v.y);
        __nv_bfloat16 h2 = __float2bfloat16_rn(v.z);
        __nv_bfloat16 h3 = __float2bfloat16_rn(v.w);
        __nv_bfloat16 l0 = __float2bfloat16_rn(v.x - __bfloat162float(h0));
        __nv_bfloat16 l1 = __float2bfloat16_rn(v.y - __bfloat162float(h1));
        __nv_bfloat16 l2 = __float2bfloat16_rn(v.z - __bfloat162float(h2));
        __nv_bfloat16 l3 = __float2bfloat16_rn(v.w - __bfloat162float(h3));
        __nv_bfloat162 hv0 = __halves2bfloat162(h0, h1);
        __nv_bfloat162 hv1 = __halves2bfloat162(h2, h3);
        __nv_bfloat162 lv0 = __halves2bfloat162(l0, l1);
        __nv_bfloat162 lv1 = __halves2bfloat162(l2, l3);
        uint2 hv;
        hv.x = *reinterpret_cast<uint32_t*>(&hv0);
        hv.y = *reinterpret_cast<uint32_t*>(&hv1);
        uint2 lv;
        lv.x = *reinterpret_cast<uint32_t*>(&lv0);
        lv.y = *reinterpret_cast<uint32_t*>(&lv1);
        ((uint2*)hi)[idx] = hv;
        ((uint2*)lo)[idx] = lv;
    }
}

// ---------------- router ----------------------------------------------------
__global__ void router_kernel(const float* __restrict__ x,
                              const float* __restrict__ Wr) {
    __shared__ __align__(16) float sWr[NEXP * DDIM];
    for (int i = threadIdx.x; i < NEXP * DDIM; i += blockDim.x) {
        sWr[i] = Wr[i];
    }
    __syncthreads();

    const int warp = threadIdx.x >> 5;
    const int lane = threadIdx.x & 31;
    const int t = blockIdx.x * 8 + warp;

    const float4* xr = (const float4*)(x + (size_t)t * DDIM);
    const float4* wr = (const float4*)sWr;

    float acc[NEXP];
#pragma unroll
    for (int e = 0; e < NEXP; e++) {
        acc[e] = 0.f;
    }

    for (int i = lane; i < DDIM / 4; i += 32) {
        float4 xv = xr[i];
#pragma unroll
        for (int e = 0; e < NEXP; e++) {
            float4 wv = wr[e * (DDIM / 4) + i];
            acc[e] += xv.x * wv.x + xv.y * wv.y + xv.z * wv.z + xv.w * wv.w;
        }
    }
#pragma unroll
    for (int e = 0; e < NEXP; e++) {
#pragma unroll
        for (int off = 16; off; off >>= 1) {
            acc[e] += __shfl_xor_sync(0xffffffffu, acc[e], off);
        }
    }

    if (lane == 0) {
        int i1 = 0;
        float m1 = acc[0];
#pragma unroll
        for (int e = 1; e < NEXP; e++) {
            if (acc[e] > m1) { m1 = acc[e]; i1 = e; }
        }
        int i2 = -1;
        float m2 = -INFINITY;
#pragma unroll
        for (int e = 0; e < NEXP; e++) {
            if (e != i1 && acc[e] > m2) { m2 = acc[e]; i2 = e; }
        }

        float w1 = 1.0f / (1.0f + expf(m2 - m1));
        float w2 = 1.0f - w1;

        int p1 = atomicAdd(&g_count[i1], 1);
        g_tok[i1][p1] = t;
        int p2 = atomicAdd(&g_count[i2], 1);
        g_tok[i2][p2] = t;
        g_assign[t] = make_int4(i1, p1, i2, p2);
        g_tw[t] = make_float2(w1, w2);
    }
}

__global__ void prefix_kernel() {
    if (threadIdx.x == 0) {
        int s = 0;
#pragma unroll
        for (int e = 0; e < NEXP; e++) {
            g_base[e] = s;
            s += g_count[e];
        }
    }
}

// ============================================================================
// bf16x3 tensor-core grouped GEMM, 3-stage cp.async pipeline.
// C[m,n] = sum_k A[m,k]*B[n,k]
// EPI 0: A = gathered x rows (bf16 hi/lo), B = W1[e], gelu(c+b1) -> g_Hh/g_Hl
// EPI 1: A = packed H rows,               B = W2[e], raw c      -> g_Y
// ============================================================================
template <int EPI>
__global__ void __launch_bounds__(256, 2)
gemm_mma_kernel(const float* __restrict__ bias) {
    const int e    = blockIdx.z;
    const int cnt  = g_count[e];
    const int row0 = blockIdx.y * BM;
    if (row0 >= cnt) { return; }
    const int col0 = blockIdx.x * BN;
    const int base = g_base[e];

    extern __shared__ __align__(128) char dsmem[];
    const uint32_t sb = smem_u32(dsmem);

    const int tid  = threadIdx.x;
    const int lane = tid & 31;
    const int wid  = tid >> 5;

    // ---- cp.async source pointers (per thread: 2 A rows + 1 B row, hi+lo) ----
    const int rowq = tid >> 2;     // 0..63
    const int cq   = tid & 3;      // 16B chunk within 64B k-slab
    const uint32_t oA0 = (uint32_t)rowq * 80u + (uint32_t)cq * 16u;
    const uint32_t oA1 = (uint32_t)(rowq + 64) * 80u + (uint32_t)cq * 16u;

    const __nv_bfloat16* aH0;
    const __nv_bfloat16* aL0;
    const __nv_bfloat16* aH1;
    const __nv_bfloat16* aL1;
    const __nv_bfloat16* bHp;
    const __nv_bfloat16* bLp;
    {
        int r0 = row0 + rowq;
        int r1 = row0 + rowq + 64;
        if (r0 >= cnt) { r0 = cnt - 1; }
        if (r1 >= cnt) { r1 = cnt - 1; }
        if (EPI == 0) {
            const int t0 = g_tok[e][r0];
            const int t1 = g_tok[e][r1];
            aH0 = g_xh + (size_t)t0 * DDIM + cq * 8;
            aL0 = g_xl + (size_t)t0 * DDIM + cq * 8;
            aH1 = g_xh + (size_t)t1 * DDIM + cq * 8;
            aL1 = g_xl + (size_t)t1 * DDIM + cq * 8;
            bHp = g_w1h + ((size_t)e * DDIM + col0 + rowq) * DDIM + cq * 8;
            bLp = g_w1l + ((size_t)e * DDIM + col0 + rowq) * DDIM + cq * 8;
        } else {
            aH0 = g_Hh + (size_t)(base + r0) * DDIM + cq * 8;
            aL0 = g_Hl + (size_t)(base + r0) * DDIM + cq * 8;
            aH1 = g_Hh + (size_t)(base + r1) * DDIM + cq * 8;
            aL1 = g_Hl + (size_t)(base + r1) * DDIM + cq * 8;
            bHp = g_w2h + ((size_t)e * DDIM + col0 + rowq) * DDIM + cq * 8;
            bLp = g_w2l + ((size_t)e * DDIM + col0 + rowq) * DDIM + cq * 8;
        }
    }

    // ---- mma fragment smem offsets (bf16 elems) -------------------------------
    const int wm = (wid & 3) * 32;
    const int wn = (wid >> 2) * 32;
    const int aLd = (wm + (lane & 15)) * LDR + ((lane >> 4) << 3);
    const int bLd = (wn + ((lane >> 4) << 3) + (lane & 7)) * LDR + (lane & 8);

    float acc[2][4][4];
#pragma unroll
    for (int i = 0; i < 2; i++) {
#pragma unroll
        for (int j = 0; j < 4; j++) {
#pragma unroll
            for (int q = 0; q < 4; q++) {
                acc[i][j][q] = 0.f;
            }
        }
    }

    // ---- prologue: fill stages 0,1 --------------------------------------------
#pragma unroll
    for (int s = 0; s < 2; s++) {
        const uint32_t st = sb + (uint32_t)s * STAGE_BYTES;
        const int k0 = s * BK;
        cp16(st + OFF_AH + oA0, aH0 + k0);
        cp16(st + OFF_AH + oA1, aH1 + k0);
        cp16(st + OFF_AL + oA0, aL0 + k0);
        cp16(st + OFF_AL + oA1, aL1 + k0);
        cp16(st + OFF_BH + oA0, bHp + k0);
        cp16(st + OFF_BL + oA0, bLp + k0);
        cp_commit();
    }

    // ---- mainloop ---------------------------------------------------------------
    for (int i = 0; i < NITER; i++) {
        cp_wait1();
        __syncthreads();

        // refill the stage read two iters ago
        if (i + 2 < NITER) {
            const int sn = (i + 2) % NSTAGE;
            const uint32_t st = sb + (uint32_t)sn * STAGE_BYTES;
            const int k0 = (i + 2) * BK;
            cp16(st + OFF_AH + oA0, aH0 + k0);
            cp16(st + OFF_AH + oA1, aH1 + k0);
            cp16(st + OFF_AL + oA0, aL0 + k0);
            cp16(st + OFF_AL + oA1, aL1 + k0);
            cp16(st + OFF_BH + oA0, bHp + k0);
            cp16(st + OFF_BL + oA0, bLp + k0);
        }
        cp_commit();

        const int b = i % NSTAGE;
        const __nv_bfloat16* sAh = (const __nv_bfloat16*)(dsmem + b * STAGE_BYTES + OFF_AH);
        const __nv_bfloat16* sAl = (const __nv_bfloat16*)(dsmem + b * STAGE_BYTES + OFF_AL);
        const __nv_bfloat16* sBh = (const __nv_bfloat16*)(dsmem + b * STAGE_BYTES + OFF_BH);
        const __nv_bfloat16* sBl = (const __nv_bfloat16*)(dsmem + b * STAGE_BYTES + OFF_BL);

#pragma unroll
        for (int kk = 0; kk < BK; kk += 16) {
            uint32_t ah0[4];
            uint32_t ah1[4];
            uint32_t al0[4];
            uint32_t al1[4];
            uint32_t bh0[4];
            uint32_t bh1[4];
            uint32_t bl0[4];
            uint32_t bl1[4];
            ldsm4(ah0, sAh + aLd + kk);
            ldsm4(ah1, sAh + aLd + 16 * LDR + kk);
            ldsm4(al0, sAl + aLd + kk);
            ldsm4(al1, sAl + aLd + 16 * LDR + kk);
            ldsm4(bh0, sBh + bLd + kk);
            ldsm4(bh1, sBh + bLd + 16 * LDR + kk);
            ldsm4(bl0, sBl + bLd + kk);
            ldsm4(bl1, sBl + bLd + 16 * LDR + kk);

            mma16816(acc[0][0], ah0, &bh0[0]);
            mma16816(acc[0][1], ah0, &bh0[2]);
            mma16816(acc[0][2], ah0, &bh1[0]);
            mma16816(acc[0][3], ah0, &bh1[2]);
            mma16816(acc[1][0], ah1, &bh0[0]);
            mma16816(acc[1][1], ah1, &bh0[2]);
            mma16816(acc[1][2], ah1, &bh1[0]);
            mma16816(acc[1][3], ah1, &bh1[2]);

            mma16816(acc[0][0], ah0, &bl0[0]);
            mma16816(acc[0][1], ah0, &bl0[2]);
            mma16816(acc[0][2], ah0, &bl1[0]);
            mma16816(acc[0][3], ah0, &bl1[2]);
            mma16816(acc[1][0], ah1, &bl0[0]);
            mma16816(acc[1][1], ah1, &bl0[2]);
            mma16816(acc[1][2], ah1, &bl1[0]);
            mma16816(acc[1][3], ah1, &bl1[2]);

            mma16816(acc[0][0], al0, &bh0[0]);
            mma16816(acc[0][1], al0, &bh0[2]);
            mma16816(acc[0][2], al0, &bh1[0]);
            mma16816(acc[0][3], al0, &bh1[2]);
            mma16816(acc[1][0], al1, &bh0[0]);
            mma16816(acc[1][1], al1, &bh0[2]);
            mma16816(acc[1][2], al1, &bh1[0]);
            mma16816(acc[1][3], al1, &bh1[2]);
        }
    }

    // ---- epilogue ----------------------------------------------------------------
    const int r0l = lane >> 2;
    const int c0l = (lane & 3) * 2;
#pragma unroll
    for (int mt = 0; mt < 2; mt++) {
#pragma unroll
        for (int nt = 0; nt < 4; nt++) {
            const int fc = col0 + wn + nt * 8 + c0l;
#pragma unroll
            for (int half = 0; half < 2; half++) {
                const int r = row0 + wm + mt * 16 + r0l + half * 8;
                if (r < cnt) {
                    float v0 = acc[mt][nt][half * 2 + 0];
                    float v1 = acc[mt][nt][half * 2 + 1];
                    if (EPI == 0) {
                        float2 bb = *(const float2*)(bias + (size_t)e * DDIM + fc);
                        v0 += bb.x;
                        v1 += bb.y;
                        v0 = 0.5f * v0 * (1.0f + erff(v0 * 0.70710678118654752f));
                        v1 = 0.5f * v1 * (1.0f + erff(v1 * 0.70710678118654752f));
                        __nv_bfloat16 h0 = __float2bfloat16_rn(v0);
                        __nv_bfloat16 h1 = __float2bfloat16_rn(v1);
                        __nv_bfloat16 l0 = __float2bfloat16_rn(v0 - __bfloat162float(h0));
                        __nv_bfloat16 l1 = __float2bfloat16_rn(v1 - __bfloat162float(h1));
                        *(__nv_bfloat162*)(g_Hh + (size_t)(base + r) * DDIM + fc) =
                            __halves2bfloat162(h0, h1);
                        *(__nv_bfloat162*)(g_Hl + (size_t)(base + r) * DDIM + fc) =
                            __halves2bfloat162(l0, l1);
                    } else {
                        *(float2*)(g_Y + (size_t)(base + r) * DDIM + fc) = make_float2(v0, v1);
                    }
                }
            }
        }
    }
}

// ---------------- combine: out[t] = w1*(y1+b2[e1]) + w2*(y2+b2[e2]) ----------
__global__ void combine_kernel(const float* __restrict__ b2,
                               float* __restrict__ out) {
    const int idx = blockIdx.x * blockDim.x + threadIdx.x;
    const int t = idx >> 8;        // DDIM/4 = 256 float4 per token
    const int c4 = idx & 255;
    int4 a = g_assign[t];
    float2 w = g_tw[t];
    const int s1 = g_base[a.x] + a.y;
    const int s2 = g_base[a.z] + a.w;
    float4 y1 = *(const float4*)(g_Y + (size_t)s1 * DDIM + c4 * 4);
    float4 y2 = *(const float4*)(g_Y + (size_t)s2 * DDIM + c4 * 4);
    float4 v1 = *(const float4*)(b2 + (size_t)a.x * DDIM + c4 * 4);
    float4 v2 = *(const float4*)(b2 + (size_t)a.z * DDIM + c4 * 4);
    float4 o;
    o.x = w.x * (y1.x + v1.x) + w.y * (y2.x + v2.x);
    o.y = w.x * (y1.y + v1.y) + w.y * (y2.y + v2.y);
    o.z = w.x * (y1.z + v1.z) + w.y * (y2.z + v2.z);
    o.w = w.x * (y1.w + v1.w) + w.y * (y2.w + v2.w);
    ((float4*)out)[idx] = o;
}

// ---------------- launch -----------------------------------------------------
extern "C" void kernel_launch(void* const* d_in, const int* in_sizes, int n_in,
                              void* d_out, int out_size) {
    const float* x  = (const float*)d_in[0];
    const float* Wr = (const float*)d_in[1];
    const float* W1 = (const float*)d_in[2];
    const float* b1 = (const float*)d_in[3];
    const float* W2 = (const float*)d_in[4];
    const float* b2 = (const float*)d_in[5];
    float* out = (float*)d_out;

    cudaFuncSetAttribute(gemm_mma_kernel<0>,
                         cudaFuncAttributeMaxDynamicSharedMemorySize, SMEM_DYN);
    cudaFuncSetAttribute(gemm_mma_kernel<1>,
                         cudaFuncAttributeMaxDynamicSharedMemorySize, SMEM_DYN);

    init_counts_kernel<<<1, 32>>>();
    router_kernel<<<T_TOKENS / 8, 256>>>(x, Wr);
    prefix_kernel<<<1, 32>>>();

    conv_split_kernel<<<2048, 256>>>(x,  0, (T_TOKENS * DDIM) / 4);
    conv_split_kernel<<<2048, 256>>>(W1, 1, (NEXP * DDIM * DDIM) / 4);
    conv_split_kernel<<<2048, 256>>>(W2, 2, (NEXP * DDIM * DDIM) / 4);

    dim3 grid(DDIM / BN, T_TOKENS / BM, NEXP);   // (16, 128, 8), early-exit on count
    gemm_mma_kernel<0><<<grid, 256, SMEM_DYN>>>(b1);
    gemm_mma_kernel<1><<<grid, 256, SMEM_DYN>>>(b1);

    combine_kernel<<<(T_TOKENS * DDIM / 4) / 256, 256>>>(b2, out);
}

// round 11
// speedup vs baseline: 1.0826x; 1.0826x over previous
#include <cuda_runtime.h>
#include <cuda_bf16.h>
#include <math.h>
#include <stdint.h>

// Problem constants
#define T_TOKENS 16384
#define DDIM     1024
#define NEXP     8

// GEMM tiling
#define BM 128
#define BN 64
#define BK 32
#define LDR 40                     // bf16 elems per smem row (32 data + 8 pad = 80B)
#define NITER (DDIM / BK)          // 32 slabs

// stage layout (bytes): Ah | Al | Bh | Bl
#define A_BYTES (BM * LDR * 2)     // 10240
#define B_BYTES (BN * LDR * 2)     // 5120
#define OFF_AH 0
#define OFF_AL A_BYTES
#define OFF_BH (2 * A_BYTES)
#define OFF_BL (2 * A_BYTES + B_BYTES)
#define STAGE_BYTES (2 * A_BYTES + 2 * B_BYTES)    // 30720
#define SMEM_DYN (3 * STAGE_BYTES)                 // 92160

// ---------------- scratch (static device globals; no allocation) ------------
__device__ int    g_count[NEXP];
__device__ int    g_base[NEXP];
__device__ int    g_tok[NEXP][T_TOKENS];
__device__ int4   g_assign[T_TOKENS];
__device__ float2 g_tw[T_TOKENS];

__device__ __nv_bfloat16 g_xh[T_TOKENS * DDIM];
__device__ __nv_bfloat16 g_xl[T_TOKENS * DDIM];
__device__ __nv_bfloat16 g_w1h[NEXP * DDIM * DDIM];
__device__ __nv_bfloat16 g_w1l[NEXP * DDIM * DDIM];
__device__ __nv_bfloat16 g_w2h[NEXP * DDIM * DDIM];
__device__ __nv_bfloat16 g_w2l[NEXP * DDIM * DDIM];
__device__ __nv_bfloat16 g_Hh[2 * T_TOKENS * DDIM];
__device__ __nv_bfloat16 g_Hl[2 * T_TOKENS * DDIM];
__device__ float         g_Y[2 * T_TOKENS * DDIM];

// ---------------- helpers ----------------------------------------------------
static __device__ __forceinline__ uint32_t smem_u32(const void* p) {
    uint32_t a;
    asm("{ .reg .u64 t; cvta.to.shared.u64 t, %1; cvt.u32.u64 %0, t; }"
        : "=r"(a) : "l"(p));
    return a;
}
static __device__ __forceinline__ void cp16(uint32_t dst, const void* src) {
    asm volatile("cp.async.cg.shared.global [%0], [%1], 16;" :: "r"(dst), "l"(src));
}
static __device__ __forceinline__ void cp_commit() {
    asm volatile("cp.async.commit_group;" ::: "memory");
}
static __device__ __forceinline__ void cp_wait1() {
    asm volatile("cp.async.wait_group 1;" ::: "memory");
}

static __device__ __forceinline__ void ldsm4(uint32_t* r, const __nv_bfloat16* p) {
    uint32_t a = (uint32_t)__cvta_generic_to_shared(p);
    asm volatile("ldmatrix.sync.aligned.m8n8.x4.shared.b16 {%0,%1,%2,%3}, [%4];"
                 : "=r"(r[0]), "=r"(r[1]), "=r"(r[2]), "=r"(r[3])
                 : "r"(a));
}
static __device__ __forceinline__ void mma16816(float* c, const uint32_t* a, const uint32_t* b) {
    asm volatile("mma.sync.aligned.m16n8k16.row.col.f32.bf16.bf16.f32 "
                 "{%0,%1,%2,%3},{%4,%5,%6,%7},{%8,%9},{%0,%1,%2,%3};"
                 : "+f"(c[0]), "+f"(c[1]), "+f"(c[2]), "+f"(c[3])
                 : "r"(a[0]), "r"(a[1]), "r"(a[2]), "r"(a[3]),
                   "r"(b[0]), "r"(b[1]));
}

// ---------------- init ------------------------------------------------------
__global__ void init_counts_kernel() {
    if (threadIdx.x < NEXP) {
        g_count[threadIdx.x] = 0;
    }
}

// ---------------- fp32 -> bf16 hi/lo split conversion ------------------------
__global__ void conv_split_kernel(const float* __restrict__ src, int which, int n4) {
    __nv_bfloat16* hi;
    __nv_bfloat16* lo;
    if (which == 0)      { hi = g_xh;  lo = g_xl;  }
    else if (which == 1) { hi = g_w1h; lo = g_w1l; }
    else                 { hi = g_w2h; lo = g_w2l; }

    int idx = blockIdx.x * blockDim.x + threadIdx.x;
    const int stride = gridDim.x * blockDim.x;
    for (; idx < n4; idx += stride) {
        float4 v = ((const float4*)src)[idx];
        __nv_bfloat16 h0 = __float2bfloat16_rn(v.x);
        __nv_bfloat16 h1 = __float2bfloat16_rn(v.y);
        __nv_bfloat16 h2 = __float2bfloat16_rn(v.z);
        __nv_bfloat16 h3 = __float2bfloat16_rn(v.w);
        __nv_bfloat16 l0 = __float2bfloat16_rn(v.x - __bfloat162float(h0));
        __nv_bfloat16 l1 = __float2bfloat16_rn(v.y - __bfloat162float(h1));
        __nv_bfloat16 l2 = __float2bfloat16_rn(v.z - __bfloat162float(h2));
        __nv_bfloat16 l3 = __float2bfloat16_rn(v.w - __bfloat162float(h3));
        __nv_bfloat162 hv0 = __halves2bfloat162(h0, h1);
        __nv_bfloat162 hv1 = __halves2bfloat162(h2, h3);
        __nv_bfloat162 lv0 = __halves2bfloat162(l0, l1);
        __nv_bfloat162 lv1 = __halves2bfloat162(l2, l3);
        uint2 hv;
        hv.x = *reinterpret_cast<uint32_t*>(&hv0);
        hv.y = *reinterpret_cast<uint32_t*>(&hv1);
        uint2 lv;
        lv.x = *reinterpret_cast<uint32_t*>(&lv0);
        lv.y = *reinterpret_cast<uint32_t*>(&lv1);
        ((uint2*)hi)[idx] = hv;
        ((uint2*)lo)[idx] = lv;
    }
}

// ---------------- router ----------------------------------------------------
__global__ void router_kernel(const float* __restrict__ x,
                              const float* __restrict__ Wr) {
    __shared__ __align__(16) float sWr[NEXP * DDIM];
    for (int i = threadIdx.x; i < NEXP * DDIM; i += blockDim.x) {
        sWr[i] = Wr[i];
    }
    __syncthreads();

    const int warp = threadIdx.x >> 5;
    const int lane = threadIdx.x & 31;
    const int t = blockIdx.x * 8 + warp;

    const float4* xr = (const float4*)(x + (size_t)t * DDIM);
    const float4* wr = (const float4*)sWr;

    float acc[NEXP];
#pragma unroll
    for (int e = 0; e < NEXP; e++) {
        acc[e] = 0.f;
    }

    for (int i = lane; i < DDIM / 4; i += 32) {
        float4 xv = xr[i];
#pragma unroll
        for (int e = 0; e < NEXP; e++) {
            float4 wv = wr[e * (DDIM / 4) + i];
            acc[e] += xv.x * wv.x + xv.y * wv.y + xv.z * wv.z + xv.w * wv.w;
        }
    }
#pragma unroll
    for (int e = 0; e < NEXP; e++) {
#pragma unroll
        for (int off = 16; off; off >>= 1) {
            acc[e] += __shfl_xor_sync(0xffffffffu, acc[e], off);
        }
    }

    if (lane == 0) {
        int i1 = 0;
        float m1 = acc[0];
#pragma unroll
        for (int e = 1; e < NEXP; e++) {
            if (acc[e] > m1) { m1 = acc[e]; i1 = e; }
        }
        int i2 = -1;
        float m2 = -INFINITY;
#pragma unroll
        for (int e = 0; e < NEXP; e++) {
            if (e != i1 && acc[e] > m2) { m2 = acc[e]; i2 = e; }
        }

        float w1 = 1.0f / (1.0f + expf(m2 - m1));
        float w2 = 1.0f - w1;

        int p1 = atomicAdd(&g_count[i1], 1);
        g_tok[i1][p1] = t;
        int p2 = atomicAdd(&g_count[i2], 1);
        g_tok[i2][p2] = t;
        g_assign[t] = make_int4(i1, p1, i2, p2);
        g_tw[t] = make_float2(w1, w2);
    }
}

__global__ void prefix_kernel() {
    if (threadIdx.x == 0) {
        int s = 0;
#pragma unroll
        for (int e = 0; e < NEXP; e++) {
            g_base[e] = s;
            s += g_count[e];
        }
    }
}

// ---------------- gemm building blocks ---------------------------------------
static __device__ __forceinline__ void refill_stage(
    uint32_t st, int k0,
    const __nv_bfloat16* aH0, const __nv_bfloat16* aH1,
    const __nv_bfloat16* aL0, const __nv_bfloat16* aL1,
    const __nv_bfloat16* bHp, const __nv_bfloat16* bLp,
    uint32_t oA0, uint32_t oA1) {
    cp16(st + OFF_AH + oA0, aH0 + k0);
    cp16(st + OFF_AH + oA1, aH1 + k0);
    cp16(st + OFF_AL + oA0, aL0 + k0);
    cp16(st + OFF_AL + oA1, aL1 + k0);
    cp16(st + OFF_BH + oA0, bHp + k0);
    cp16(st + OFF_BL + oA0, bLp + k0);
}

static __device__ __forceinline__ void compute_slab(
    const __nv_bfloat16* sAh, const __nv_bfloat16* sAl,
    const __nv_bfloat16* sBh, const __nv_bfloat16* sBl,
    int aLd, int bLd, float acc[2][4][4]) {
#pragma unroll
    for (int kk = 0; kk < BK; kk += 16) {
        uint32_t ah0[4];
        uint32_t ah1[4];
        uint32_t al0[4];
        uint32_t al1[4];
        uint32_t bh0[4];
        uint32_t bh1[4];
        uint32_t bl0[4];
        uint32_t bl1[4];
        ldsm4(ah0, sAh + aLd + kk);
        ldsm4(ah1, sAh + aLd + 16 * LDR + kk);
        ldsm4(al0, sAl + aLd + kk);
        ldsm4(al1, sAl + aLd + 16 * LDR + kk);
        ldsm4(bh0, sBh + bLd + kk);
        ldsm4(bh1, sBh + bLd + 16 * LDR + kk);
        ldsm4(bl0, sBl + bLd + kk);
        ldsm4(bl1, sBl + bLd + 16 * LDR + kk);

        mma16816(acc[0][0], ah0, &bh0[0]);
        mma16816(acc[0][1], ah0, &bh0[2]);
        mma16816(acc[0][2], ah0, &bh1[0]);
        mma16816(acc[0][3], ah0, &bh1[2]);
        mma16816(acc[1][0], ah1, &bh0[0]);
        mma16816(acc[1][1], ah1, &bh0[2]);
        mma16816(acc[1][2], ah1, &bh1[0]);
        mma16816(acc[1][3], ah1, &bh1[2]);

        mma16816(acc[0][0], ah0, &bl0[0]);
        mma16816(acc[0][1], ah0, &bl0[2]);
        mma16816(acc[0][2], ah0, &bl1[0]);
        mma16816(acc[0][3], ah0, &bl1[2]);
        mma16816(acc[1][0], ah1, &bl0[0]);
        mma16816(acc[1][1], ah1, &bl0[2]);
        mma16816(acc[1][2], ah1, &bl1[0]);
        mma16816(acc[1][3], ah1, &bl1[2]);

        mma16816(acc[0][0], al0, &bh0[0]);
        mma16816(acc[0][1], al0, &bh0[2]);
        mma16816(acc[0][2], al0, &bh1[0]);
        mma16816(acc[0][3], al0, &bh1[2]);
        mma16816(acc[1][0], al1, &bh0[0]);
        mma16816(acc[1][1], al1, &bh0[2]);
        mma16816(acc[1][2], al1, &bh1[0]);
        mma16816(acc[1][3], al1, &bh1[2]);
    }
}

// ============================================================================
// bf16x3 tensor-core grouped GEMM, 3-stage cp.async pipeline, stage rotation
// unrolled at compile time so all SMEM addresses are loop-invariant.
// C[m,n] = sum_k A[m,k]*B[n,k]
// EPI 0: A = gathered x rows (bf16 hi/lo), B = W1[e], gelu(c+b1) -> g_Hh/g_Hl
// EPI 1: A = packed H rows,               B = W2[e], raw c      -> g_Y
// ============================================================================
template <int EPI>
__global__ void __launch_bounds__(256, 2)
gemm_mma_kernel(const float* __restrict__ bias) {
    const int e    = blockIdx.z;
    const int cnt  = g_count[e];
    const int row0 = blockIdx.y * BM;
    if (row0 >= cnt) { return; }
    const int col0 = blockIdx.x * BN;
    const int base = g_base[e];

    extern __shared__ __align__(128) char dsmem[];
    const uint32_t sb = smem_u32(dsmem);

    const int tid  = threadIdx.x;
    const int lane = tid & 31;
    const int wid  = tid >> 5;

    // ---- cp.async source pointers (per thread: 2 A rows + 1 B row, hi+lo) ----
    const int rowq = tid >> 2;     // 0..63
    const int cq   = tid & 3;      // 16B chunk within 64B k-slab
    const uint32_t oA0 = (uint32_t)rowq * 80u + (uint32_t)cq * 16u;
    const uint32_t oA1 = (uint32_t)(rowq + 64) * 80u + (uint32_t)cq * 16u;

    const __nv_bfloat16* aH0;
    const __nv_bfloat16* aL0;
    const __nv_bfloat16* aH1;
    const __nv_bfloat16* aL1;
    const __nv_bfloat16* bHp;
    const __nv_bfloat16* bLp;
    {
        int r0 = row0 + rowq;
        int r1 = row0 + rowq + 64;
        if (r0 >= cnt) { r0 = cnt - 1; }
        if (r1 >= cnt) { r1 = cnt - 1; }
        if (EPI == 0) {
            const int t0 = g_tok[e][r0];
            const int t1 = g_tok[e][r1];
            aH0 = g_xh + (size_t)t0 * DDIM + cq * 8;
            aL0 = g_xl + (size_t)t0 * DDIM + cq * 8;
            aH1 = g_xh + (size_t)t1 * DDIM + cq * 8;
            aL1 = g_xl + (size_t)t1 * DDIM + cq * 8;
            bHp = g_w1h + ((size_t)e * DDIM + col0 + rowq) * DDIM + cq * 8;
            bLp = g_w1l + ((size_t)e * DDIM + col0 + rowq) * DDIM + cq * 8;
        } else {
            aH0 = g_Hh + (size_t)(base + r0) * DDIM + cq * 8;
            aL0 = g_Hl + (size_t)(base + r0) * DDIM + cq * 8;
            aH1 = g_Hh + (size_t)(base + r1) * DDIM + cq * 8;
            aL1 = g_Hl + (size_t)(base + r1) * DDIM + cq * 8;
            bHp = g_w2h + ((size_t)e * DDIM + col0 + rowq) * DDIM + cq * 8;
            bLp = g_w2l + ((size_t)e * DDIM + col0 + rowq) * DDIM + cq * 8;
        }
    }

    // ---- constant per-stage bases ----------------------------------------------
    const uint32_t st0 = sb;
    const uint32_t st1 = sb + STAGE_BYTES;
    const uint32_t st2 = sb + 2 * STAGE_BYTES;
    const __nv_bfloat16* s0Ah = (const __nv_bfloat16*)(dsmem + 0 * STAGE_BYTES + OFF_AH);
    const __nv_bfloat16* s0Al = (const __nv_bfloat16*)(dsmem + 0 * STAGE_BYTES + OFF_AL);
    const __nv_bfloat16* s0Bh = (const __nv_bfloat16*)(dsmem + 0 * STAGE_BYTES + OFF_BH);
    const __nv_bfloat16* s0Bl = (const __nv_bfloat16*)(dsmem + 0 * STAGE_BYTES + OFF_BL);
    const __nv_bfloat16* s1Ah = (const __nv_bfloat16*)(dsmem + 1 * STAGE_BYTES + OFF_AH);
    const __nv_bfloat16* s1Al = (const __nv_bfloat16*)(dsmem + 1 * STAGE_BYTES + OFF_AL);
    const __nv_bfloat16* s1Bh = (const __nv_bfloat16*)(dsmem + 1 * STAGE_BYTES + OFF_BH);
    const __nv_bfloat16* s1Bl = (const __nv_bfloat16*)(dsmem + 1 * STAGE_BYTES + OFF_BL);
    const __nv_bfloat16* s2Ah = (const __nv_bfloat16*)(dsmem + 2 * STAGE_BYTES + OFF_AH);
    const __nv_bfloat16* s2Al = (const __nv_bfloat16*)(dsmem + 2 * STAGE_BYTES + OFF_AL);
    const __nv_bfloat16* s2Bh = (const __nv_bfloat16*)(dsmem + 2 * STAGE_BYTES + OFF_BH);
    const __nv_bfloat16* s2Bl = (const __nv_bfloat16*)(dsmem + 2 * STAGE_BYTES + OFF_BL);

    // ---- mma fragment smem offsets (bf16 elems) -------------------------------
    const int wm = (wid & 3) * 32;
    const int wn = (wid >> 2) * 32;
    const int aLd = (wm + (lane & 15)) * LDR + ((lane >> 4) << 3);
    const int bLd = (wn + ((lane >> 4) << 3) + (lane & 7)) * LDR + (lane & 8);

    float acc[2][4][4];
#pragma unroll
    for (int i = 0; i < 2; i++) {
#pragma unroll
        for (int j = 0; j < 4; j++) {
#pragma unroll
            for (int q = 0; q < 4; q++) {
                acc[i][j][q] = 0.f;
            }
        }
    }

    // ---- prologue: slabs 0,1 into stages 0,1 -----------------------------------
    refill_stage(st0, 0 * BK, aH0, aH1, aL0, aL1, bHp, bLp, oA0, oA1);
    cp_commit();
    refill_stage(st1, 1 * BK, aH0, aH1, aL0, aL1, bHp, bLp, oA0, oA1);
    cp_commit();

    // ---- mainloop: slab j uses stage j%3; refill stage (j+2)%3 with slab j+2 ---
    for (int j = 0; j < 30; j += 3) {
        // slab j  (stage 0), refill stage 2 <- slab j+2
        cp_wait1();
        __syncthreads();
        refill_stage(st2, (j + 2) * BK, aH0, aH1, aL0, aL1, bHp, bLp, oA0, oA1);
        cp_commit();
        compute_slab(s0Ah, s0Al, s0Bh, s0Bl, aLd, bLd, acc);

        // slab j+1 (stage 1), refill stage 0 <- slab j+3
        cp_wait1();
        __syncthreads();
        refill_stage(st0, (j + 3) * BK, aH0, aH1, aL0, aL1, bHp, bLp, oA0, oA1);
        cp_commit();
        compute_slab(s1Ah, s1Al, s1Bh, s1Bl, aLd, bLd, acc);

        // slab j+2 (stage 2), refill stage 1 <- slab j+4 (skip if OOB)
        cp_wait1();
        __syncthreads();
        if (j + 4 < NITER) {
            refill_stage(st1, (j + 4) * BK, aH0, aH1, aL0, aL1, bHp, bLp, oA0, oA1);
        }
        cp_commit();
        compute_slab(s2Ah, s2Al, s2Bh, s2Bl, aLd, bLd, acc);
    }

    // ---- tail: slabs 30 (stage 0) and 31 (stage 1), no refills ------------------
    cp_wait1();
    __syncthreads();
    cp_commit();
    compute_slab(s0Ah, s0Al, s0Bh, s0Bl, aLd, bLd, acc);

    cp_wait1();
    __syncthreads();
    cp_commit();
    compute_slab(s1Ah, s1Al, s1Bh, s1Bl, aLd, bLd, acc);

    // ---- epilogue ----------------------------------------------------------------
    const int r0l = lane >> 2;
    const int c0l = (lane & 3) * 2;
#pragma unroll
    for (int mt = 0; mt < 2; mt++) {
#pragma unroll
        for (int nt = 0; nt < 4; nt++) {
            const int fc = col0 + wn + nt * 8 + c0l;
#pragma unroll
            for (int half = 0; half < 2; half++) {
                const int r = row0 + wm + mt * 16 + r0l + half * 8;
                if (r < cnt) {
                    float v0 = acc[mt][nt][half * 2 + 0];
                    float v1 = acc[mt][nt][half * 2 + 1];
                    if (EPI == 0) {
                        float2 bb = *(const float2*)(bias + (size_t)e * DDIM + fc);
                        v0 += bb.x;
                        v1 += bb.y;
                        v0 = 0.5f * v0 * (1.0f + erff(v0 * 0.70710678118654752f));
                        v1 = 0.5f * v1 * (1.0f + erff(v1 * 0.70710678118654752f));
                        __nv_bfloat16 h0 = __float2bfloat16_rn(v0);
                        __nv_bfloat16 h1 = __float2bfloat16_rn(v1);
                        __nv_bfloat16 l0 = __float2bfloat16_rn(v0 - __bfloat162float(h0));
                        __nv_bfloat16 l1 = __float2bfloat16_rn(v1 - __bfloat162float(h1));
                        *(__nv_bfloat162*)(g_Hh + (size_t)(base + r) * DDIM + fc) =
                            __halves2bfloat162(h0, h1);
                        *(__nv_bfloat162*)(g_Hl + (size_t)(base + r) * DDIM + fc) =
                            __halves2bfloat162(l0, l1);
                    } else {
                        *(float2*)(g_Y + (size_t)(base + r) * DDIM + fc) = make_float2(v0, v1);
                    }
                }
            }
        }
    }
}

// ---------------- combine: out[t] = w1*(y1+b2[e1]) + w2*(y2+b2[e2]) ----------
__global__ void combine_kernel(const float* __restrict__ b2,
                               float* __restrict__ out) {
    const int idx = blockIdx.x * blockDim.x + threadIdx.x;
    const int t = idx >> 8;        // DDIM/4 = 256 float4 per token
    const int c4 = idx & 255;
    int4 a = g_assign[t];
    float2 w = g_tw[t];
    const int s1 = g_base[a.x] + a.y;
    const int s2 = g_base[a.z] + a.w;
    float4 y1 = *(const float4*)(g_Y + (size_t)s1 * DDIM + c4 * 4);
    float4 y2 = *(const float4*)(g_Y + (size_t)s2 * DDIM + c4 * 4);
    float4 v1 = *(const float4*)(b2 + (size_t)a.x * DDIM + c4 * 4);
    float4 v2 = *(const float4*)(b2 + (size_t)a.z * DDIM + c4 * 4);
    float4 o;
    o.x = w.x * (y1.x + v1.x) + w.y * (y2.x + v2.x);
    o.y = w.x * (y1.y + v1.y) + w.y * (y2.y + v2.y);
    o.z = w.x * (y1.z + v1.z) + w.y * (y2.z + v2.z);
    o.w = w.x * (y1.w + v1.w) + w.y * (y2.w + v2.w);
    ((float4*)out)[idx] = o;
}

// ---------------- launch -----------------------------------------------------
extern "C" void kernel_launch(void* const* d_in, const int* in_sizes, int n_in,
                              void* d_out, int out_size) {
    const float* x  = (const float*)d_in[0];
    const float* Wr = (const float*)d_in[1];
    const float* W1 = (const float*)d_in[2];
    const float* b1 = (const float*)d_in[3];
    const float* W2 = (const float*)d_in[4];
    const float* b2 = (const float*)d_in[5];
    float* out = (float*)d_out;

    cudaFuncSetAttribute(gemm_mma_kernel<0>,
                         cudaFuncAttributeMaxDynamicSharedMemorySize, SMEM_DYN);
    cudaFuncSetAttribute(gemm_mma_kernel<1>,
                         cudaFuncAttributeMaxDynamicSharedMemorySize, SMEM_DYN);

    init_counts_kernel<<<1, 32>>>();
    router_kernel<<<T_TOKENS / 8, 256>>>(x, Wr);
    prefix_kernel<<<1, 32>>>();

    conv_split_kernel<<<2048, 256>>>(x,  0, (T_TOKENS * DDIM) / 4);
    conv_split_kernel<<<2048, 256>>>(W1, 1, (NEXP * DDIM * DDIM) / 4);
    conv_split_kernel<<<2048, 256>>>(W2, 2, (NEXP * DDIM * DDIM) / 4);

    dim3 grid(DDIM / BN, T_TOKENS / BM, NEXP);   // (16, 128, 8), early-exit on count
    gemm_mma_kernel<0><<<grid, 256, SMEM_DYN>>>(b1);
    gemm_mma_kernel<1><<<grid, 256, SMEM_DYN>>>(b1);

    combine_kernel<<<(T_TOKENS * DDIM / 4) / 256, 256>>>(b2, out);
}